// round 4
// baseline (speedup 1.0000x reference)
#include <cuda_runtime.h>
#include <cuda_bf16.h>
#include <cstdint>

#define NROWS 8192
#define DDIM  128
#define BM    128
#define BN    128
#define INV_N2 1.4901161193847656e-08f   // 2^-26

#define ROWB   272                        // padded smem row stride in bytes (17*16)
#define SMEM_A_OFF 0
#define SMEM_B_OFF (128 * ROWB)           // 34816
#define SMEM_RED_OFF (2 * 128 * ROWB)     // 69632
#define SMEM_BYTES (SMEM_RED_OFF + 64)

// bf16 normalized copies (scratch via __device__ globals; no allocation)
__device__ __nv_bfloat16 g_xb[NROWS * DDIM];
__device__ __nv_bfloat16 g_yb[NROWS * DDIM];

__device__ __forceinline__ uint32_t smem_u32(const void* p) {
    uint32_t a;
    asm("{ .reg .u64 t; cvta.to.shared.u64 t, %1; cvt.u32.u64 %0, t; }" : "=r"(a) : "l"(p));
    return a;
}

__device__ __forceinline__ void ldmatrix_x4(uint32_t& r0, uint32_t& r1,
                                            uint32_t& r2, uint32_t& r3, uint32_t addr) {
    asm volatile("ldmatrix.sync.aligned.m8n8.x4.shared.b16 {%0,%1,%2,%3}, [%4];"
                 : "=r"(r0), "=r"(r1), "=r"(r2), "=r"(r3) : "r"(addr));
}

__device__ __forceinline__ void mma16816(float& d0, float& d1, float& d2, float& d3,
                                         uint32_t a0, uint32_t a1, uint32_t a2, uint32_t a3,
                                         uint32_t b0, uint32_t b1) {
    asm volatile("mma.sync.aligned.m16n8k16.row.col.f32.bf16.bf16.f32 "
                 "{%0,%1,%2,%3}, {%4,%5,%6,%7}, {%8,%9}, {%0,%1,%2,%3};"
                 : "+f"(d0), "+f"(d1), "+f"(d2), "+f"(d3)
                 : "r"(a0), "r"(a1), "r"(a2), "r"(a3), "r"(b0), "r"(b1));
}

// ---------------------------------------------------------------------------
// Kernel A: normalize rows in fp32, emit bf16
// ---------------------------------------------------------------------------
__global__ void normalize_kernel(const float* __restrict__ x,
                                 const float* __restrict__ y) {
    int b = blockIdx.x;
    const float* src;
    __nv_bfloat16* dst;
    if (b < NROWS) { src = x + (size_t)b * DDIM;           dst = g_xb + (size_t)b * DDIM; }
    else           { src = y + (size_t)(b - NROWS) * DDIM; dst = g_yb + (size_t)(b - NROWS) * DDIM; }

    float v = src[threadIdx.x];
    float ss = v * v;
    #pragma unroll
    for (int o = 16; o > 0; o >>= 1) ss += __shfl_xor_sync(0xffffffffu, ss, o);

    __shared__ float wsum[4];
    int wid = threadIdx.x >> 5;
    if ((threadIdx.x & 31) == 0) wsum[wid] = ss;
    __syncthreads();
    float tot = wsum[0] + wsum[1] + wsum[2] + wsum[3];
    dst[threadIdx.x] = __float2bfloat16_rn(v * rsqrtf(fmaxf(tot, 1e-24f)));
}

// ---------------------------------------------------------------------------
// Kernel B: bf16 mma.sync GEMM (128x128 CTA tile, K=128 resident) + fused loss.
// 4 warps in 2(m) x 2(n); warp tile 64x64 = 4x8 m16n8k16 fragments.
// 2 CTAs/SM so one CTA's tile fill overlaps the other's MMA phase.
// ---------------------------------------------------------------------------
extern __shared__ char dyn_smem[];

__global__ void __launch_bounds__(128, 2)
gemm_loss_kernel(float* __restrict__ out) {
    const int tid  = threadIdx.x;
    const int warp = tid >> 5;
    const int lane = tid & 31;
    const int bm = blockIdx.y;
    const int bn = blockIdx.x;
    const int wm = warp & 1;          // 0..1 (64-row half)
    const int wn = warp >> 1;         // 0..1 (64-col half)

    char* sA = dyn_smem + SMEM_A_OFF;
    char* sB = dyn_smem + SMEM_B_OFF;

    // ---- Fill SMEM tiles (padded rows, coalesced 16B loads) ----
    {
        const uint4* __restrict__ xsrc = (const uint4*)(g_xb + (size_t)(bm * BM) * DDIM);
        const uint4* __restrict__ ysrc = (const uint4*)(g_yb + (size_t)(bn * BN) * DDIM);
        #pragma unroll
        for (int it = 0; it < 16; it++) {
            int c = it * 128 + tid;        // 0..2047 16B chunks; 16 chunks per row
            int r = c >> 4;
            int v = c & 15;
            *(uint4*)(sA + r * ROWB + v * 16) = xsrc[c];
            *(uint4*)(sB + r * ROWB + v * 16) = ysrc[c];
        }
    }
    __syncthreads();

    // ---- ldmatrix address precompute ----
    const uint32_t sA32 = smem_u32(sA);
    const uint32_t sB32 = smem_u32(sB);
    const int t8 = lane & 7;
    // A x4: matrices = (m0-7,k0-7),(m8-15,k0-7),(m0-7,k8-15),(m8-15,k8-15)
    const uint32_t aRow = (uint32_t)(wm * 64 + t8 + ((lane >> 3) & 1) * 8);
    const uint32_t aBase = sA32 + aRow * ROWB + (uint32_t)(lane >> 4) * 16;
    // B x4: matrices = (n0-7,k0-7),(n0-7,k8-15),(n8-15,k0-7),(n8-15,k8-15)
    const uint32_t bRow = (uint32_t)(wn * 64 + ((lane >> 4) * 8) + t8);
    const uint32_t bBase = sB32 + bRow * ROWB + (uint32_t)((lane >> 3) & 1) * 16;

    float acc[4][8][4];
    #pragma unroll
    for (int i = 0; i < 4; i++)
        #pragma unroll
        for (int j = 0; j < 8; j++)
            #pragma unroll
            for (int e = 0; e < 4; e++) acc[i][j][e] = 0.0f;

    // ---- Main loop: 8 k-steps of 16; 8 LDSM.x4 feed 32 MMAs per step ----
    #pragma unroll
    for (int ks = 0; ks < 8; ks++) {
        uint32_t a[4][4];
        uint32_t b[4][4];
        #pragma unroll
        for (int mt = 0; mt < 4; mt++)
            ldmatrix_x4(a[mt][0], a[mt][1], a[mt][2], a[mt][3],
                        aBase + (uint32_t)(mt * 16) * ROWB + (uint32_t)ks * 32);
        #pragma unroll
        for (int bi = 0; bi < 4; bi++)
            ldmatrix_x4(b[bi][0], b[bi][1], b[bi][2], b[bi][3],
                        bBase + (uint32_t)(bi * 16) * ROWB + (uint32_t)ks * 32);

        #pragma unroll
        for (int mt = 0; mt < 4; mt++) {
            #pragma unroll
            for (int nt = 0; nt < 8; nt++) {
                const int bi = nt >> 1;
                const int po = (nt & 1) * 2;
                mma16816(acc[mt][nt][0], acc[mt][nt][1], acc[mt][nt][2], acc[mt][nt][3],
                         a[mt][0], a[mt][1], a[mt][2], a[mt][3],
                         b[bi][po], b[bi][po + 1]);
            }
        }
    }

    // ---- Fused epilogue: diag / relu + reduce ----
    // d0: (row=lane>>2, col=(lane&3)*2)  d1: col+1  d2: row+8  d3: row+8,col+1
    const int gm0 = bm * BM + wm * 64 + (lane >> 2);
    const int gn0 = bn * BN + wn * 64 + (lane & 3) * 2;
    float lsum = 0.0f;
    #pragma unroll
    for (int mt = 0; mt < 4; mt++) {
        const int gmA = gm0 + mt * 16;
        const int gmB = gmA + 8;
        #pragma unroll
        for (int nt = 0; nt < 8; nt++) {
            const int gn = gn0 + nt * 8;
            float s0 = acc[mt][nt][0], s1 = acc[mt][nt][1];
            float s2 = acc[mt][nt][2], s3 = acc[mt][nt][3];
            lsum += (gmA == gn    ) ? (1.0f - s0) : fmaxf(s0, 0.0f);
            lsum += (gmA == gn + 1) ? (1.0f - s1) : fmaxf(s1, 0.0f);
            lsum += (gmB == gn    ) ? (1.0f - s2) : fmaxf(s2, 0.0f);
            lsum += (gmB == gn + 1) ? (1.0f - s3) : fmaxf(s3, 0.0f);
        }
    }

    #pragma unroll
    for (int o = 16; o > 0; o >>= 1) lsum += __shfl_xor_sync(0xffffffffu, lsum, o);
    float* red = (float*)(dyn_smem + SMEM_RED_OFF);
    if (lane == 0) red[warp] = lsum;
    __syncthreads();
    if (tid == 0) {
        atomicAdd(out, (red[0] + red[1] + red[2] + red[3]) * INV_N2);
    }
}

// ---------------------------------------------------------------------------
extern "C" void kernel_launch(void* const* d_in, const int* in_sizes, int n_in,
                              void* d_out, int out_size) {
    const float* x = (const float*)d_in[0];
    const float* y = (const float*)d_in[1];
    float* out = (float*)d_out;

    cudaFuncSetAttribute(gemm_loss_kernel,
                         cudaFuncAttributeMaxDynamicSharedMemorySize, SMEM_BYTES);

    cudaMemsetAsync(out, 0, sizeof(float));
    normalize_kernel<<<2 * NROWS, DDIM>>>(x, y);
    dim3 grid(NROWS / BN, NROWS / BM);
    gemm_loss_kernel<<<grid, 128, SMEM_BYTES>>>(out);
}

// round 5
// speedup vs baseline: 1.1372x; 1.1372x over previous
#include <cuda_runtime.h>
#include <cuda_bf16.h>
#include <cstdint>

#define NROWS 8192
#define DDIM  128
#define BM    128
#define BN    128
#define NTILE 64                          // tiles per dimension
#define TOTTILES (NTILE * NTILE)          // 4096
#define GRIDSZ 296                        // 2 CTAs per SM (148 SMs)
#define INV_N2 1.4901161193847656e-08f    // 2^-26

#define ROWB   272                        // padded smem row stride (17*16 bytes)
#define TILEB  (128 * ROWB)               // 34816 bytes per tile
#define SMEM_A_OFF 0
#define SMEM_B0_OFF TILEB
#define SMEM_B1_OFF (2 * TILEB)
#define SMEM_RED_OFF (3 * TILEB)          // 104448
#define SMEM_BYTES (SMEM_RED_OFF + 64)

// bf16 normalized copies (scratch via __device__ globals; no allocation)
__device__ __nv_bfloat16 g_xb[NROWS * DDIM];
__device__ __nv_bfloat16 g_yb[NROWS * DDIM];

__device__ __forceinline__ uint32_t smem_u32(const void* p) {
    uint32_t a;
    asm("{ .reg .u64 t; cvta.to.shared.u64 t, %1; cvt.u32.u64 %0, t; }" : "=r"(a) : "l"(p));
    return a;
}
__device__ __forceinline__ void cp_async16(uint32_t dst, const void* src) {
    asm volatile("cp.async.cg.shared.global [%0], [%1], 16;" :: "r"(dst), "l"(src));
}
__device__ __forceinline__ void cp_commit() {
    asm volatile("cp.async.commit_group;" ::: "memory");
}
__device__ __forceinline__ void cp_wait0() {
    asm volatile("cp.async.wait_group 0;" ::: "memory");
}
__device__ __forceinline__ void ldmatrix_x4(uint32_t& r0, uint32_t& r1,
                                            uint32_t& r2, uint32_t& r3, uint32_t addr) {
    asm volatile("ldmatrix.sync.aligned.m8n8.x4.shared.b16 {%0,%1,%2,%3}, [%4];"
                 : "=r"(r0), "=r"(r1), "=r"(r2), "=r"(r3) : "r"(addr));
}
__device__ __forceinline__ void mma16816(float& d0, float& d1, float& d2, float& d3,
                                         uint32_t a0, uint32_t a1, uint32_t a2, uint32_t a3,
                                         uint32_t b0, uint32_t b1) {
    asm volatile("mma.sync.aligned.m16n8k16.row.col.f32.bf16.bf16.f32 "
                 "{%0,%1,%2,%3}, {%4,%5,%6,%7}, {%8,%9}, {%0,%1,%2,%3};"
                 : "+f"(d0), "+f"(d1), "+f"(d2), "+f"(d3)
                 : "r"(a0), "r"(a1), "r"(a2), "r"(a3), "r"(b0), "r"(b1));
}

// ---------------------------------------------------------------------------
// Kernel A: normalize rows in fp32, emit bf16
// ---------------------------------------------------------------------------
__global__ void normalize_kernel(const float* __restrict__ x,
                                 const float* __restrict__ y) {
    int b = blockIdx.x;
    const float* src;
    __nv_bfloat16* dst;
    if (b < NROWS) { src = x + (size_t)b * DDIM;           dst = g_xb + (size_t)b * DDIM; }
    else           { src = y + (size_t)(b - NROWS) * DDIM; dst = g_yb + (size_t)(b - NROWS) * DDIM; }

    float v = src[threadIdx.x];
    float ss = v * v;
    #pragma unroll
    for (int o = 16; o > 0; o >>= 1) ss += __shfl_xor_sync(0xffffffffu, ss, o);

    __shared__ float wsum[4];
    int wid = threadIdx.x >> 5;
    if ((threadIdx.x & 31) == 0) wsum[wid] = ss;
    __syncthreads();
    float tot = wsum[0] + wsum[1] + wsum[2] + wsum[3];
    dst[threadIdx.x] = __float2bfloat16_rn(v * rsqrtf(fmaxf(tot, 1e-24f)));
}

// ---------------------------------------------------------------------------
// Kernel B: persistent bf16 mma.sync GEMM + fused loss.
// 8 warps in 2(m) x 4(n); warp tile 64x32 = 4x4 m16n8k16 fragments.
// Each CTA walks a contiguous row-major run of tiles: A reloaded only on bm
// change; B double-buffered and prefetched via cp.async during MMA compute.
// ---------------------------------------------------------------------------
extern __shared__ char dyn_smem[];

__global__ void __launch_bounds__(256, 2)
gemm_loss_kernel(float* __restrict__ out) {
    const int tid  = threadIdx.x;
    const int warp = tid >> 5;
    const int lane = tid & 31;
    const int wm = warp & 1;          // 0..1 (64-row halves)
    const int wn = warp >> 1;         // 0..3 (32-col quarters)

    const uint32_t sbase = smem_u32(dyn_smem);
    const uint32_t sA32  = sbase + SMEM_A_OFF;

    // loader mapping: thread moves 8 16B-chunks per tile (2048 chunks total)
    // chunk c -> row r = c>>4, 16B-slot v = c&15; smem offset r*ROWB + v*16
    uint32_t ld_off[8];
    #pragma unroll
    for (int it = 0; it < 8; it++) {
        int c = it * 256 + tid;
        ld_off[it] = (uint32_t)(c >> 4) * ROWB + (uint32_t)(c & 15) * 16;
    }

    // ldmatrix address precompute (offsets relative to tile base)
    const int t8 = lane & 7;
    const uint32_t aRow = (uint32_t)(wm * 64 + t8 + ((lane >> 3) & 1) * 8);
    const uint32_t aOff = aRow * ROWB + (uint32_t)(lane >> 4) * 16;
    const uint32_t bRow = (uint32_t)(wn * 32 + ((lane >> 4) * 8) + t8);
    const uint32_t bOff = bRow * ROWB + (uint32_t)((lane >> 3) & 1) * 16;

    // tile run for this CTA
    const int per = (TOTTILES + GRIDSZ - 1) / GRIDSZ;     // 14
    int start = blockIdx.x * per;
    int end   = start + per;
    if (start > TOTTILES) start = TOTTILES;
    if (end   > TOTTILES) end   = TOTTILES;

    float lsum = 0.0f;
    int cur_bm = -1;
    bool next_prefetched = false;

    for (int t = start; t < end; t++) {
        const int bm = t >> 6;
        const int bn = t & 63;
        const uint32_t sBcur = sbase + ((t & 1) ? SMEM_B1_OFF : SMEM_B0_OFF);

        if (bm != cur_bm) {
            // fresh A (and B, never prefetched across a bm change)
            __syncthreads();   // all warps done with old tiles
            const char* asrc = (const char*)(g_xb + (size_t)(bm * BM) * DDIM);
            const char* bsrc = (const char*)(g_yb + (size_t)(bn * BN) * DDIM);
            #pragma unroll
            for (int it = 0; it < 8; it++) {
                cp_async16(sA32 + ld_off[it],  asrc + it * 4096 + (tid << 4));
                cp_async16(sBcur + ld_off[it], bsrc + it * 4096 + (tid << 4));
            }
            cp_commit();
            cp_wait0();
            __syncthreads();
            cur_bm = bm;
        } else {
            // B for this tile was prefetched last iteration
            cp_wait0();
            __syncthreads();
        }

        // prefetch next B if next tile shares this bm (overlaps with MMA below)
        next_prefetched = false;
        if (t + 1 < end && ((t + 1) >> 6) == bm) {
            const uint32_t sBnext = sbase + (((t + 1) & 1) ? SMEM_B1_OFF : SMEM_B0_OFF);
            const char* bsrc = (const char*)(g_yb + (size_t)((t + 1) & 63) * BN * DDIM);
            #pragma unroll
            for (int it = 0; it < 8; it++)
                cp_async16(sBnext + ld_off[it], bsrc + it * 4096 + (tid << 4));
            cp_commit();
            next_prefetched = true;
        }

        // ---- MMA: 8 k-steps of 16 ----
        float acc[4][4][4];
        #pragma unroll
        for (int i = 0; i < 4; i++)
            #pragma unroll
            for (int j = 0; j < 4; j++)
                #pragma unroll
                for (int e = 0; e < 4; e++) acc[i][j][e] = 0.0f;

        #pragma unroll
        for (int ks = 0; ks < 8; ks++) {
            uint32_t a[4][4];
            uint32_t b[2][4];
            #pragma unroll
            for (int mt = 0; mt < 4; mt++)
                ldmatrix_x4(a[mt][0], a[mt][1], a[mt][2], a[mt][3],
                            sA32 + aOff + (uint32_t)(mt * 16) * ROWB + (uint32_t)ks * 32);
            #pragma unroll
            for (int bi = 0; bi < 2; bi++)
                ldmatrix_x4(b[bi][0], b[bi][1], b[bi][2], b[bi][3],
                            sBcur + bOff + (uint32_t)(bi * 16) * ROWB + (uint32_t)ks * 32);

            #pragma unroll
            for (int mt = 0; mt < 4; mt++) {
                #pragma unroll
                for (int nt = 0; nt < 4; nt++) {
                    const int bi = nt >> 1;
                    const int po = (nt & 1) * 2;
                    mma16816(acc[mt][nt][0], acc[mt][nt][1], acc[mt][nt][2], acc[mt][nt][3],
                             a[mt][0], a[mt][1], a[mt][2], a[mt][3],
                             b[bi][po], b[bi][po + 1]);
                }
            }
        }

        // ---- fused loss map, accumulate across tiles ----
        const int gm0 = bm * BM + wm * 64 + (lane >> 2);
        const int gn0 = bn * BN + wn * 32 + (lane & 3) * 2;
        #pragma unroll
        for (int mt = 0; mt < 4; mt++) {
            const int gmA = gm0 + mt * 16;
            const int gmB = gmA + 8;
            #pragma unroll
            for (int nt = 0; nt < 4; nt++) {
                const int gn = gn0 + nt * 8;
                float s0 = acc[mt][nt][0], s1 = acc[mt][nt][1];
                float s2 = acc[mt][nt][2], s3 = acc[mt][nt][3];
                lsum += (gmA == gn    ) ? (1.0f - s0) : fmaxf(s0, 0.0f);
                lsum += (gmA == gn + 1) ? (1.0f - s1) : fmaxf(s1, 0.0f);
                lsum += (gmB == gn    ) ? (1.0f - s2) : fmaxf(s2, 0.0f);
                lsum += (gmB == gn + 1) ? (1.0f - s3) : fmaxf(s3, 0.0f);
            }
        }
        // NOTE: no __syncthreads here; the one at loop top orders buffer reuse.
    }
    (void)next_prefetched;

    // ---- final block reduction + single atomic ----
    #pragma unroll
    for (int o = 16; o > 0; o >>= 1) lsum += __shfl_xor_sync(0xffffffffu, lsum, o);
    float* red = (float*)(dyn_smem + SMEM_RED_OFF);
    __syncthreads();
    if (lane == 0) red[warp] = lsum;
    __syncthreads();
    if (tid == 0) {
        float tot = 0.0f;
        #pragma unroll
        for (int w = 0; w < 8; w++) tot += red[w];
        atomicAdd(out, tot * INV_N2);
    }
}

// ---------------------------------------------------------------------------
extern "C" void kernel_launch(void* const* d_in, const int* in_sizes, int n_in,
                              void* d_out, int out_size) {
    const float* x = (const float*)d_in[0];
    const float* y = (const float*)d_in[1];
    float* out = (float*)d_out;

    cudaFuncSetAttribute(gemm_loss_kernel,
                         cudaFuncAttributeMaxDynamicSharedMemorySize, SMEM_BYTES);

    cudaMemsetAsync(out, 0, sizeof(float));
    normalize_kernel<<<2 * NROWS, DDIM>>>(x, y);
    gemm_loss_kernel<<<GRIDSZ, 256, SMEM_BYTES>>>(out);
}

// round 6
// speedup vs baseline: 1.3210x; 1.1617x over previous
#include <cuda_runtime.h>
#include <cuda_bf16.h>
#include <cstdint>

#define NROWS 8192
#define DDIM  128
#define BM    128
#define BN    128
#define NTILE 64
#define TOTTILES (NTILE * NTILE)          // 4096
#define GRIDSZ 296                        // 2 CTAs per SM
#define INV_N2 1.4901161193847656e-08f    // 2^-26

#define ROWB   272                        // padded smem row stride (17*16 bytes)
#define TILEB  (128 * ROWB)               // 34816 bytes per tile
#define SMEM_A_OFF 0
#define SMEM_B0_OFF TILEB
#define SMEM_B1_OFF (2 * TILEB)
#define SMEM_RED_OFF (3 * TILEB)
#define SMEM_BYTES (SMEM_RED_OFF + 64)

__device__ __nv_bfloat16 g_xb[NROWS * DDIM];
__device__ __nv_bfloat16 g_yb[NROWS * DDIM];

__device__ __forceinline__ uint32_t smem_u32(const void* p) {
    uint32_t a;
    asm("{ .reg .u64 t; cvta.to.shared.u64 t, %1; cvt.u32.u64 %0, t; }" : "=r"(a) : "l"(p));
    return a;
}
__device__ __forceinline__ void cp_async16(uint32_t dst, const void* src) {
    asm volatile("cp.async.cg.shared.global [%0], [%1], 16;" :: "r"(dst), "l"(src));
}
__device__ __forceinline__ void cp_commit() {
    asm volatile("cp.async.commit_group;" ::: "memory");
}
__device__ __forceinline__ void cp_wait0() {
    asm volatile("cp.async.wait_group 0;" ::: "memory");
}
__device__ __forceinline__ void ldmatrix_x4(uint32_t& r0, uint32_t& r1,
                                            uint32_t& r2, uint32_t& r3, uint32_t addr) {
    asm volatile("ldmatrix.sync.aligned.m8n8.x4.shared.b16 {%0,%1,%2,%3}, [%4];"
                 : "=r"(r0), "=r"(r1), "=r"(r2), "=r"(r3) : "r"(addr));
}
__device__ __forceinline__ void mma16816(float& d0, float& d1, float& d2, float& d3,
                                         uint32_t a0, uint32_t a1, uint32_t a2, uint32_t a3,
                                         uint32_t b0, uint32_t b1) {
    asm volatile("mma.sync.aligned.m16n8k16.row.col.f32.bf16.bf16.f32 "
                 "{%0,%1,%2,%3}, {%4,%5,%6,%7}, {%8,%9}, {%0,%1,%2,%3};"
                 : "+f"(d0), "+f"(d1), "+f"(d2), "+f"(d3)
                 : "r"(a0), "r"(a1), "r"(a2), "r"(a3), "r"(b0), "r"(b1));
}

// ---------------------------------------------------------------------------
// Kernel A: warp-per-row normalize, float4 loads, bf16x2 stores
// ---------------------------------------------------------------------------
__global__ void __launch_bounds__(256)
normalize_kernel(const float* __restrict__ x, const float* __restrict__ y) {
    const int row  = blockIdx.x * 8 + (threadIdx.x >> 5);
    const int lane = threadIdx.x & 31;
    const float* src;
    __nv_bfloat16* dst;
    if (row < NROWS) { src = x + (size_t)row * DDIM;           dst = g_xb + (size_t)row * DDIM; }
    else             { src = y + (size_t)(row - NROWS) * DDIM; dst = g_yb + (size_t)(row - NROWS) * DDIM; }

    float4 v = ((const float4*)src)[lane];
    float ss = v.x * v.x + v.y * v.y + v.z * v.z + v.w * v.w;
    #pragma unroll
    for (int o = 16; o > 0; o >>= 1) ss += __shfl_xor_sync(0xffffffffu, ss, o);
    float r = rsqrtf(fmaxf(ss, 1e-24f));

    __nv_bfloat162 p0 = __floats2bfloat162_rn(v.x * r, v.y * r);
    __nv_bfloat162 p1 = __floats2bfloat162_rn(v.z * r, v.w * r);
    uint2 pk;
    pk.x = *(uint32_t*)&p0;
    pk.y = *(uint32_t*)&p1;
    ((uint2*)dst)[lane] = pk;
}

// ---------------------------------------------------------------------------
// Kernel B: persistent bf16 mma.sync GEMM + fused loss.
// 8 warps, warp tile 64x32. B double-buffered via cp.async across tiles;
// ldmatrix fragments double-buffered across k-steps (software pipeline).
// ---------------------------------------------------------------------------
extern __shared__ char dyn_smem[];

__global__ void __launch_bounds__(256, 2)
gemm_loss_kernel(float* __restrict__ out) {
    const int tid  = threadIdx.x;
    const int warp = tid >> 5;
    const int lane = tid & 31;
    const int wm = warp & 1;
    const int wn = warp >> 1;

    const uint32_t sbase = smem_u32(dyn_smem);
    const uint32_t sA32  = sbase + SMEM_A_OFF;

    uint32_t ld_off[8];
    #pragma unroll
    for (int it = 0; it < 8; it++) {
        int c = it * 256 + tid;
        ld_off[it] = (uint32_t)(c >> 4) * ROWB + (uint32_t)(c & 15) * 16;
    }

    const int t8 = lane & 7;
    const uint32_t aRow = (uint32_t)(wm * 64 + t8 + ((lane >> 3) & 1) * 8);
    const uint32_t aOff = aRow * ROWB + (uint32_t)(lane >> 4) * 16;
    const uint32_t bRow = (uint32_t)(wn * 32 + ((lane >> 4) * 8) + t8);
    const uint32_t bOff = bRow * ROWB + (uint32_t)((lane >> 3) & 1) * 16;

    // balanced tile split: first `rem` CTAs get per+1 tiles
    const int per = TOTTILES / GRIDSZ;                 // 13
    const int rem = TOTTILES - per * GRIDSZ;           // 248
    int start, cnt;
    if ((int)blockIdx.x < rem) { cnt = per + 1; start = blockIdx.x * cnt; }
    else                       { cnt = per;     start = rem * (per + 1) + ((int)blockIdx.x - rem) * per; }
    const int end = start + cnt;

    float lsum = 0.0f;
    int cur_bm = -1;

    for (int t = start; t < end; t++) {
        const int bm = t >> 6;
        const int bn = t & 63;
        const uint32_t sBcur = sbase + ((t & 1) ? SMEM_B1_OFF : SMEM_B0_OFF);

        if (bm != cur_bm) {
            __syncthreads();
            const char* asrc = (const char*)(g_xb + (size_t)(bm * BM) * DDIM);
            const char* bsrc = (const char*)(g_yb + (size_t)(bn * BN) * DDIM);
            #pragma unroll
            for (int it = 0; it < 8; it++) {
                cp_async16(sA32 + ld_off[it],  asrc + it * 4096 + (tid << 4));
                cp_async16(sBcur + ld_off[it], bsrc + it * 4096 + (tid << 4));
            }
            cp_commit();
            cp_wait0();
            __syncthreads();
            cur_bm = bm;
        } else {
            cp_wait0();
            __syncthreads();
        }

        // prefetch next B (overlaps MMA below)
        if (t + 1 < end && ((t + 1) >> 6) == bm) {
            const uint32_t sBnext = sbase + (((t + 1) & 1) ? SMEM_B1_OFF : SMEM_B0_OFF);
            const char* bsrc = (const char*)(g_yb + (size_t)((t + 1) & 63) * BN * DDIM);
            #pragma unroll
            for (int it = 0; it < 8; it++)
                cp_async16(sBnext + ld_off[it], bsrc + it * 4096 + (tid << 4));
            cp_commit();
        }

        // ---- MMA phase: k-step software pipeline (fragment double buffer) ----
        float acc[4][4][4];
        #pragma unroll
        for (int i = 0; i < 4; i++)
            #pragma unroll
            for (int j = 0; j < 4; j++)
                #pragma unroll
                for (int e = 0; e < 4; e++) acc[i][j][e] = 0.0f;

        uint32_t a[2][4][4];
        uint32_t b[2][2][4];

        // prologue: fragments for k-step 0
        #pragma unroll
        for (int mt = 0; mt < 4; mt++)
            ldmatrix_x4(a[0][mt][0], a[0][mt][1], a[0][mt][2], a[0][mt][3],
                        sA32 + aOff + (uint32_t)(mt * 16) * ROWB);
        #pragma unroll
        for (int bi = 0; bi < 2; bi++)
            ldmatrix_x4(b[0][bi][0], b[0][bi][1], b[0][bi][2], b[0][bi][3],
                        sBcur + bOff + (uint32_t)(bi * 16) * ROWB);

        #pragma unroll
        for (int ks = 0; ks < 8; ks++) {
            const int cur = ks & 1;
            const int nxt = cur ^ 1;
            if (ks < 7) {
                const uint32_t ko = (uint32_t)(ks + 1) * 32;
                #pragma unroll
                for (int mt = 0; mt < 4; mt++)
                    ldmatrix_x4(a[nxt][mt][0], a[nxt][mt][1], a[nxt][mt][2], a[nxt][mt][3],
                                sA32 + aOff + (uint32_t)(mt * 16) * ROWB + ko);
                #pragma unroll
                for (int bi = 0; bi < 2; bi++)
                    ldmatrix_x4(b[nxt][bi][0], b[nxt][bi][1], b[nxt][bi][2], b[nxt][bi][3],
                                sBcur + bOff + (uint32_t)(bi * 16) * ROWB + ko);
            }
            #pragma unroll
            for (int mt = 0; mt < 4; mt++) {
                #pragma unroll
                for (int nt = 0; nt < 4; nt++) {
                    const int bi = nt >> 1;
                    const int po = (nt & 1) * 2;
                    mma16816(acc[mt][nt][0], acc[mt][nt][1], acc[mt][nt][2], acc[mt][nt][3],
                             a[cur][mt][0], a[cur][mt][1], a[cur][mt][2], a[cur][mt][3],
                             b[cur][bi][po], b[cur][bi][po + 1]);
                }
            }
        }

        // ---- fused loss map ----
        if (bm != bn) {
            // off-diagonal tile: pure relu-sum
            #pragma unroll
            for (int mt = 0; mt < 4; mt++)
                #pragma unroll
                for (int nt = 0; nt < 4; nt++)
                    #pragma unroll
                    for (int e = 0; e < 4; e++)
                        lsum += fmaxf(acc[mt][nt][e], 0.0f);
        } else {
            const int gm0 = wm * 64 + (lane >> 2);          // local row in tile
            const int gn0 = wn * 32 + (lane & 3) * 2;       // local col in tile
            #pragma unroll
            for (int mt = 0; mt < 4; mt++) {
                const int gmA = gm0 + mt * 16;
                const int gmB = gmA + 8;
                #pragma unroll
                for (int nt = 0; nt < 4; nt++) {
                    const int gn = gn0 + nt * 8;
                    float s0 = acc[mt][nt][0], s1 = acc[mt][nt][1];
                    float s2 = acc[mt][nt][2], s3 = acc[mt][nt][3];
                    lsum += (gmA == gn    ) ? (1.0f - s0) : fmaxf(s0, 0.0f);
                    lsum += (gmA == gn + 1) ? (1.0f - s1) : fmaxf(s1, 0.0f);
                    lsum += (gmB == gn    ) ? (1.0f - s2) : fmaxf(s2, 0.0f);
                    lsum += (gmB == gn + 1) ? (1.0f - s3) : fmaxf(s3, 0.0f);
                }
            }
        }
    }

    // ---- final block reduction + single atomic ----
    #pragma unroll
    for (int o = 16; o > 0; o >>= 1) lsum += __shfl_xor_sync(0xffffffffu, lsum, o);
    float* red = (float*)(dyn_smem + SMEM_RED_OFF);
    __syncthreads();
    if (lane == 0) red[warp] = lsum;
    __syncthreads();
    if (tid == 0) {
        float tot = 0.0f;
        #pragma unroll
        for (int w = 0; w < 8; w++) tot += red[w];
        atomicAdd(out, tot * INV_N2);
    }
}

// ---------------------------------------------------------------------------
extern "C" void kernel_launch(void* const* d_in, const int* in_sizes, int n_in,
                              void* d_out, int out_size) {
    const float* x = (const float*)d_in[0];
    const float* y = (const float*)d_in[1];
    float* out = (float*)d_out;

    cudaFuncSetAttribute(gemm_loss_kernel,
                         cudaFuncAttributeMaxDynamicSharedMemorySize, SMEM_BYTES);

    cudaMemsetAsync(out, 0, sizeof(float));
    normalize_kernel<<<2 * NROWS / 8, 256>>>(x, y);
    gemm_loss_kernel<<<GRIDSZ, 256, SMEM_BYTES>>>(out);
}

// round 7
// speedup vs baseline: 1.4538x; 1.1005x over previous
#include <cuda_runtime.h>
#include <cuda_bf16.h>
#include <cstdint>

#define NROWS 8192
#define DDIM  128
#define BM    128
#define BN    128
#define NTILE 64
#define TOTTILES (NTILE * NTILE)          // 4096
#define GRIDSZ 296                        // 2 CTAs per SM
#define INV_N2 1.4901161193847656e-08f    // 2^-26

#define TILEB      32768                  // 128 rows x 256B, exact
#define SMEM_A_OFF 0
#define SMEM_B0_OFF TILEB
#define SMEM_B1_OFF (2 * TILEB)
#define SMEM_RED_OFF (3 * TILEB)          // 98304
#define SMEM_MBAR_OFF (SMEM_RED_OFF + 64)
#define SMEM_BYTES (SMEM_MBAR_OFF + 64 + 2048)   // +2KB alignment slack

// bf16 normalized copies, stored PRE-SWIZZLED: 16B chunk v of row r lives at
// slot v ^ (r & 7). A linear bulk copy then lands them swizzled in smem, and
// ldmatrix addresses XOR the same pattern -> bank-conflict-free.
__device__ __nv_bfloat16 g_xb[NROWS * DDIM];
__device__ __nv_bfloat16 g_yb[NROWS * DDIM];

__device__ __forceinline__ uint32_t smem_u32(const void* p) {
    uint32_t a;
    asm("{ .reg .u64 t; cvta.to.shared.u64 t, %1; cvt.u32.u64 %0, t; }" : "=r"(a) : "l"(p));
    return a;
}
__device__ __forceinline__ void bulk_g2s(uint32_t dst, const void* src,
                                         uint32_t bytes, uint32_t mbar) {
    asm volatile("cp.async.bulk.shared::cta.global.mbarrier::complete_tx::bytes "
                 "[%0], [%1], %2, [%3];"
                 :: "r"(dst), "l"(src), "r"(bytes), "r"(mbar) : "memory");
}
#define MBARRIER_INIT(mbar, count) \
    asm volatile("mbarrier.init.shared.b64 [%0], %1;" :: "r"((uint32_t)(mbar)), "r"((uint32_t)(count)) : "memory")
#define MBARRIER_EXPECT_TX(mbar, bytes) \
    asm volatile("mbarrier.arrive.expect_tx.shared.b64 _, [%0], %1;" :: "r"((uint32_t)(mbar)), "r"((uint32_t)(bytes)) : "memory")
#define MBARRIER_WAIT_PARITY(mbar_smem_addr, phase_parity) do { \
    uint32_t _mbar = (uint32_t)(mbar_smem_addr); \
    uint32_t _parity = (uint32_t)(phase_parity); \
    uint32_t _done; \
    asm volatile("{\n\t.reg .pred p;\n\t" \
        "mbarrier.try_wait.parity.acquire.cta.shared::cta.b64 p, [%1], %2;\n\t" \
        "selp.b32 %0, 1, 0, p;\n\t}" : "=r"(_done) : "r"(_mbar), "r"(_parity) : "memory"); \
    if (!_done) { \
        asm volatile("{\n\t.reg .pred P1;\n\t" \
            "WAIT_LOOP_%=:\n\t" \
            "mbarrier.try_wait.parity.acquire.cta.shared::cta.b64 P1, [%0], %1, 0x989680;\n\t" \
            "@P1 bra.uni WAIT_DONE_%=;\n\t" \
            "bra.uni WAIT_LOOP_%=;\n\t" \
            "WAIT_DONE_%=:\n\t}" :: "r"(_mbar), "r"(_parity) : "memory"); \
    } \
} while(0)

__device__ __forceinline__ void ldmatrix_x4(uint32_t& r0, uint32_t& r1,
                                            uint32_t& r2, uint32_t& r3, uint32_t addr) {
    asm volatile("ldmatrix.sync.aligned.m8n8.x4.shared.b16 {%0,%1,%2,%3}, [%4];"
                 : "=r"(r0), "=r"(r1), "=r"(r2), "=r"(r3) : "r"(addr));
}
__device__ __forceinline__ void mma16816(float& d0, float& d1, float& d2, float& d3,
                                         uint32_t a0, uint32_t a1, uint32_t a2, uint32_t a3,
                                         uint32_t b0, uint32_t b1) {
    asm volatile("mma.sync.aligned.m16n8k16.row.col.f32.bf16.bf16.f32 "
                 "{%0,%1,%2,%3}, {%4,%5,%6,%7}, {%8,%9}, {%0,%1,%2,%3};"
                 : "+f"(d0), "+f"(d1), "+f"(d2), "+f"(d3)
                 : "r"(a0), "r"(a1), "r"(a2), "r"(a3), "r"(b0), "r"(b1));
}

// ---------------------------------------------------------------------------
// Kernel A: warp-per-row normalize; writes swizzled gmem layout.
// Lane l handles 8B: chunk v = l>>1, half h = l&1 -> stored at chunk v^(r&7).
// ---------------------------------------------------------------------------
__global__ void __launch_bounds__(256)
normalize_kernel(const float* __restrict__ x, const float* __restrict__ y) {
    const int row  = blockIdx.x * 8 + (threadIdx.x >> 5);
    const int lane = threadIdx.x & 31;
    const float* src;
    __nv_bfloat16* dst;
    if (row < NROWS) { src = x + (size_t)row * DDIM;           dst = g_xb + (size_t)row * DDIM; }
    else             { src = y + (size_t)(row - NROWS) * DDIM; dst = g_yb + (size_t)(row - NROWS) * DDIM; }

    float4 v = ((const float4*)src)[lane];
    float ss = v.x * v.x + v.y * v.y + v.z * v.z + v.w * v.w;
    #pragma unroll
    for (int o = 16; o > 0; o >>= 1) ss += __shfl_xor_sync(0xffffffffu, ss, o);
    float r = rsqrtf(fmaxf(ss, 1e-24f));

    __nv_bfloat162 p0 = __floats2bfloat162_rn(v.x * r, v.y * r);
    __nv_bfloat162 p1 = __floats2bfloat162_rn(v.z * r, v.w * r);
    uint2 pk;
    pk.x = *(uint32_t*)&p0;
    pk.y = *(uint32_t*)&p1;

    const int vchunk = lane >> 1;
    const int half   = lane & 1;
    const int schunk = vchunk ^ (row & 7);
    ((uint2*)dst)[schunk * 2 + half] = pk;
}

// ---------------------------------------------------------------------------
// Kernel B: persistent bf16 mma.sync GEMM + fused loss.
// Tile fills via single cp.async.bulk per 32KB tile (mbarrier completion).
// 8 warps, warp tile 64x32. B double-buffered, prefetched during MMA.
// ---------------------------------------------------------------------------
extern __shared__ char dyn_smem[];

__global__ void __launch_bounds__(256, 2)
gemm_loss_kernel(float* __restrict__ out) {
    const int tid  = threadIdx.x;
    const int warp = tid >> 5;
    const int lane = tid & 31;
    const int wm = warp & 1;
    const int wn = warp >> 1;

    // 2KB-align the smem base so the swizzle bits come purely from tile offsets
    const uint32_t sbase = (smem_u32(dyn_smem) + 2047u) & ~2047u;
    const uint32_t sA   = sbase + SMEM_A_OFF;
    const uint32_t sB0  = sbase + SMEM_B0_OFF;
    const uint32_t sB1  = sbase + SMEM_B1_OFF;
    const uint32_t mbar0 = sbase + SMEM_MBAR_OFF;
    const uint32_t mbar1 = mbar0 + 8;

    if (tid == 0) { MBARRIER_INIT(mbar0, 1); MBARRIER_INIT(mbar1, 1); }
    __syncthreads();

    // ldmatrix addressing (swizzled): addr = tile + row*256 + (col ^ (t8<<4))
    const int t8 = lane & 7;
    const uint32_t sxor = (uint32_t)t8 << 4;
    const uint32_t aRow = (uint32_t)(wm * 64 + t8 + ((lane >> 3) & 1) * 8);
    const uint32_t aRB  = aRow * 256;
    const uint32_t aCol = (uint32_t)(lane >> 4) * 16;
    const uint32_t bRow = (uint32_t)(wn * 32 + ((lane >> 4) * 8) + t8);
    const uint32_t bRB  = bRow * 256;
    const uint32_t bCol = (uint32_t)((lane >> 3) & 1) * 16;

    // balanced tile split
    const int per = TOTTILES / GRIDSZ;                 // 13
    const int rem = TOTTILES - per * GRIDSZ;           // 248
    int start, cnt;
    if ((int)blockIdx.x < rem) { cnt = per + 1; start = blockIdx.x * cnt; }
    else                       { cnt = per;     start = rem * (per + 1) + ((int)blockIdx.x - rem) * per; }
    const int end = start + cnt;

    float lsum = 0.0f;
    int cur_bm = -1;
    uint32_t phase0 = 0, phase1 = 0;

    for (int t = start; t < end; t++) {
        const int bm = t >> 6;
        const int bn = t & 63;
        const int buf = t & 1;
        const uint32_t sBcur = buf ? sB1 : sB0;
        const uint32_t mcur  = buf ? mbar1 : mbar0;

        __syncthreads();   // all warps done with tile t-1 (frees buffers)

        if (bm != cur_bm) {
            // fresh A + B(t) through one mbarrier
            if (tid == 0) {
                MBARRIER_EXPECT_TX(mcur, 2 * TILEB);
                bulk_g2s(sA,    g_xb + (size_t)bm * BM * DDIM, TILEB, mcur);
                bulk_g2s(sBcur, g_yb + (size_t)bn * BN * DDIM, TILEB, mcur);
            }
            cur_bm = bm;
        }

        // prefetch next B into the other buffer (overlaps MMA below)
        if (t + 1 < end && ((t + 1) >> 6) == bm) {
            if (tid == 0) {
                const uint32_t mn = (buf ^ 1) ? mbar1 : mbar0;
                bulk_g2s((buf ^ 1) ? sB1 : sB0,
                         g_yb + (size_t)((t + 1) & 63) * BN * DDIM, TILEB, mn);
                MBARRIER_EXPECT_TX(mn, TILEB);
            }
        }

        // wait for current tile's data
        if (buf) { MBARRIER_WAIT_PARITY(mbar1, phase1); phase1 ^= 1; }
        else     { MBARRIER_WAIT_PARITY(mbar0, phase0); phase0 ^= 1; }

        // ---- MMA: 8 k-steps of 16 ----
        float acc[4][4][4];
        #pragma unroll
        for (int i = 0; i < 4; i++)
            #pragma unroll
            for (int j = 0; j < 4; j++)
                #pragma unroll
                for (int e = 0; e < 4; e++) acc[i][j][e] = 0.0f;

        #pragma unroll
        for (int ks = 0; ks < 8; ks++) {
            const uint32_t ko = (uint32_t)ks * 32;
            uint32_t a[4][4];
            uint32_t b[2][4];
            #pragma unroll
            for (int mt = 0; mt < 4; mt++)
                ldmatrix_x4(a[mt][0], a[mt][1], a[mt][2], a[mt][3],
                            sA + aRB + (uint32_t)(mt * 4096) + ((aCol + ko) ^ sxor));
            #pragma unroll
            for (int bi = 0; bi < 2; bi++)
                ldmatrix_x4(b[bi][0], b[bi][1], b[bi][2], b[bi][3],
                            sBcur + bRB + (uint32_t)(bi * 4096) + ((bCol + ko) ^ sxor));

            #pragma unroll
            for (int mt = 0; mt < 4; mt++) {
                #pragma unroll
                for (int nt = 0; nt < 4; nt++) {
                    const int bi = nt >> 1;
                    const int po = (nt & 1) * 2;
                    mma16816(acc[mt][nt][0], acc[mt][nt][1], acc[mt][nt][2], acc[mt][nt][3],
                             a[mt][0], a[mt][1], a[mt][2], a[mt][3],
                             b[bi][po], b[bi][po + 1]);
                }
            }
        }

        // ---- fused loss map ----
        if (bm != bn) {
            #pragma unroll
            for (int mt = 0; mt < 4; mt++)
                #pragma unroll
                for (int nt = 0; nt < 4; nt++)
                    #pragma unroll
                    for (int e = 0; e < 4; e++)
                        lsum += fmaxf(acc[mt][nt][e], 0.0f);
        } else {
            const int gm0 = wm * 64 + (lane >> 2);
            const int gn0 = wn * 32 + (lane & 3) * 2;
            #pragma unroll
            for (int mt = 0; mt < 4; mt++) {
                const int gmA = gm0 + mt * 16;
                const int gmB = gmA + 8;
                #pragma unroll
                for (int nt = 0; nt < 4; nt++) {
                    const int gn = gn0 + nt * 8;
                    float s0 = acc[mt][nt][0], s1 = acc[mt][nt][1];
                    float s2 = acc[mt][nt][2], s3 = acc[mt][nt][3];
                    lsum += (gmA == gn    ) ? (1.0f - s0) : fmaxf(s0, 0.0f);
                    lsum += (gmA == gn + 1) ? (1.0f - s1) : fmaxf(s1, 0.0f);
                    lsum += (gmB == gn    ) ? (1.0f - s2) : fmaxf(s2, 0.0f);
                    lsum += (gmB == gn + 1) ? (1.0f - s3) : fmaxf(s3, 0.0f);
                }
            }
        }
    }

    // ---- final block reduction + single atomic ----
    #pragma unroll
    for (int o = 16; o > 0; o >>= 1) lsum += __shfl_xor_sync(0xffffffffu, lsum, o);
    float* red = (float*)(uintptr_t)(dyn_smem + (sbase - smem_u32(dyn_smem)) + SMEM_RED_OFF);
    __syncthreads();
    if (lane == 0) red[warp] = lsum;
    __syncthreads();
    if (tid == 0) {
        float tot = 0.0f;
        #pragma unroll
        for (int w = 0; w < 8; w++) tot += red[w];
        atomicAdd(out, tot * INV_N2);
    }
}

// ---------------------------------------------------------------------------
extern "C" void kernel_launch(void* const* d_in, const int* in_sizes, int n_in,
                              void* d_out, int out_size) {
    const float* x = (const float*)d_in[0];
    const float* y = (const float*)d_in[1];
    float* out = (float*)d_out;

    cudaFuncSetAttribute(gemm_loss_kernel,
                         cudaFuncAttributeMaxDynamicSharedMemorySize, SMEM_BYTES);

    cudaMemsetAsync(out, 0, sizeof(float));
    normalize_kernel<<<2 * NROWS / 8, 256>>>(x, y);
    gemm_loss_kernel<<<GRIDSZ, 256, SMEM_BYTES>>>(out);
}

// round 8
// speedup vs baseline: 1.5045x; 1.0349x over previous
#include <cuda_runtime.h>
#include <cuda_bf16.h>
#include <cstdint>

#define NROWS 8192
#define DDIM  128
#define BM    128
#define BN    128
#define NTILE 64
#define TOTTILES (NTILE * NTILE)          // 4096
#define GRIDSZ 296                        // 2 CTAs per SM
#define INV_N2 1.4901161193847656e-08f    // 2^-26

#define TILEB      32768                  // 128 rows x 256B, exact
#define SMEM_A_OFF 0
#define SMEM_B0_OFF TILEB
#define SMEM_B1_OFF (2 * TILEB)
#define SMEM_RED_OFF (3 * TILEB)          // 98304
#define SMEM_MBAR_OFF (SMEM_RED_OFF + 64)
#define SMEM_BYTES (SMEM_MBAR_OFF + 64 + 2048)   // +2KB alignment slack

// bf16 normalized copies, stored PRE-SWIZZLED: 16B chunk v of row r lives at
// slot v ^ (r & 7); linear bulk copy lands them swizzled in smem, ldmatrix
// XORs the same pattern -> conflict-free.
__device__ __nv_bfloat16 g_xb[NROWS * DDIM];
__device__ __nv_bfloat16 g_yb[NROWS * DDIM];

__device__ __forceinline__ uint32_t smem_u32(const void* p) {
    uint32_t a;
    asm("{ .reg .u64 t; cvta.to.shared.u64 t, %1; cvt.u32.u64 %0, t; }" : "=r"(a) : "l"(p));
    return a;
}
__device__ __forceinline__ void bulk_g2s(uint32_t dst, const void* src,
                                         uint32_t bytes, uint32_t mbar) {
    asm volatile("cp.async.bulk.shared::cta.global.mbarrier::complete_tx::bytes "
                 "[%0], [%1], %2, [%3];"
                 :: "r"(dst), "l"(src), "r"(bytes), "r"(mbar) : "memory");
}
#define MBARRIER_INIT(mbar, count) \
    asm volatile("mbarrier.init.shared.b64 [%0], %1;" :: "r"((uint32_t)(mbar)), "r"((uint32_t)(count)) : "memory")
#define MBARRIER_EXPECT_TX(mbar, bytes) \
    asm volatile("mbarrier.arrive.expect_tx.shared.b64 _, [%0], %1;" :: "r"((uint32_t)(mbar)), "r"((uint32_t)(bytes)) : "memory")
#define MBARRIER_ARRIVE(mbar) \
    asm volatile("mbarrier.arrive.shared.b64 _, [%0];" :: "r"((uint32_t)(mbar)) : "memory")

#define MBARRIER_WAIT_PARITY(mbar_smem_addr, phase_parity) do { \
    uint32_t _mbar = (uint32_t)(mbar_smem_addr); \
    uint32_t _parity = (uint32_t)(phase_parity); \
    uint32_t _done; \
    asm volatile("{\n\t.reg .pred p;\n\t" \
        "mbarrier.try_wait.parity.acquire.cta.shared::cta.b64 p, [%1], %2;\n\t" \
        "selp.b32 %0, 1, 0, p;\n\t}" : "=r"(_done) : "r"(_mbar), "r"(_parity) : "memory"); \
    if (!_done) { \
        asm volatile("{\n\t.reg .pred P1;\n\t" \
            "WAIT_LOOP_%=:\n\t" \
            "mbarrier.try_wait.parity.acquire.cta.shared::cta.b64 P1, [%0], %1, 0x989680;\n\t" \
            "@P1 bra.uni WAIT_DONE_%=;\n\t" \
            "bra.uni WAIT_LOOP_%=;\n\t" \
            "WAIT_DONE_%=:\n\t}" :: "r"(_mbar), "r"(_parity) : "memory"); \
    } \
} while(0)

// Relaxed: producer-only; post-wait smem access is async-proxy (TMA).
#define MBARRIER_WAIT_PARITY_RELAXED(mbar_smem_addr, phase_parity) do { \
    uint32_t _mbar = (uint32_t)(mbar_smem_addr); \
    uint32_t _parity = (uint32_t)(phase_parity); \
    uint32_t _done; \
    asm volatile("{\n\t.reg .pred p;\n\t" \
        "mbarrier.try_wait.parity.relaxed.cta.shared::cta.b64 p, [%1], %2, 0x989680;\n\t" \
        "selp.b32 %0, 1, 0, p;\n\t}" : "=r"(_done) : "r"(_mbar), "r"(_parity) : "memory"); \
    if (!_done) { \
        asm volatile("{\n\t.reg .pred P1;\n\t" \
            "WAIT_LOOP_%=:\n\t" \
            "mbarrier.try_wait.parity.relaxed.cta.shared::cta.b64 P1, [%0], %1, 0x989680;\n\t" \
            "@P1 bra.uni WAIT_DONE_%=;\n\t" \
            "bra.uni WAIT_LOOP_%=;\n\t" \
            "WAIT_DONE_%=:\n\t}" :: "r"(_mbar), "r"(_parity) : "memory"); \
    } \
} while(0)

__device__ __forceinline__ void ldmatrix_x4(uint32_t& r0, uint32_t& r1,
                                            uint32_t& r2, uint32_t& r3, uint32_t addr) {
    asm volatile("ldmatrix.sync.aligned.m8n8.x4.shared.b16 {%0,%1,%2,%3}, [%4];"
                 : "=r"(r0), "=r"(r1), "=r"(r2), "=r"(r3) : "r"(addr));
}
__device__ __forceinline__ void mma16816(float& d0, float& d1, float& d2, float& d3,
                                         uint32_t a0, uint32_t a1, uint32_t a2, uint32_t a3,
                                         uint32_t b0, uint32_t b1) {
    asm volatile("mma.sync.aligned.m16n8k16.row.col.f32.bf16.bf16.f32 "
                 "{%0,%1,%2,%3}, {%4,%5,%6,%7}, {%8,%9}, {%0,%1,%2,%3};"
                 : "+f"(d0), "+f"(d1), "+f"(d2), "+f"(d3)
                 : "r"(a0), "r"(a1), "r"(a2), "r"(a3), "r"(b0), "r"(b1));
}

// ---------------------------------------------------------------------------
// Kernel A: warp-per-row normalize; writes swizzled gmem layout.
// ---------------------------------------------------------------------------
__global__ void __launch_bounds__(256)
normalize_kernel(const float* __restrict__ x, const float* __restrict__ y) {
    const int row  = blockIdx.x * 8 + (threadIdx.x >> 5);
    const int lane = threadIdx.x & 31;
    const float* src;
    __nv_bfloat16* dst;
    if (row < NROWS) { src = x + (size_t)row * DDIM;           dst = g_xb + (size_t)row * DDIM; }
    else             { src = y + (size_t)(row - NROWS) * DDIM; dst = g_yb + (size_t)(row - NROWS) * DDIM; }

    float4 v = ((const float4*)src)[lane];
    float ss = v.x * v.x + v.y * v.y + v.z * v.z + v.w * v.w;
    #pragma unroll
    for (int o = 16; o > 0; o >>= 1) ss += __shfl_xor_sync(0xffffffffu, ss, o);
    float r = rsqrtf(fmaxf(ss, 1e-24f));

    __nv_bfloat162 p0 = __floats2bfloat162_rn(v.x * r, v.y * r);
    __nv_bfloat162 p1 = __floats2bfloat162_rn(v.z * r, v.w * r);
    uint2 pk;
    pk.x = *(uint32_t*)&p0;
    pk.y = *(uint32_t*)&p1;

    const int vchunk = lane >> 1;
    const int half   = lane & 1;
    const int schunk = vchunk ^ (row & 7);
    ((uint2*)dst)[schunk * 2 + half] = pk;
}

// ---------------------------------------------------------------------------
// Kernel B: persistent bf16 mma.sync GEMM + fused loss.
// Per-warp producer/consumer pipeline: full[2] (count 1, expect_tx) /
// empty[2] (count 8) mbarrier pairs; NO per-tile __syncthreads. Warps skew
// freely (bounded to <=2 tiles by the empty wait), overlapping one warp's
// epilogue with another's MMA. Phase parity is a pure function of local
// tile index k (buffers alternate strictly with t).
// ---------------------------------------------------------------------------
extern __shared__ char dyn_smem[];

__global__ void __launch_bounds__(256, 2)
gemm_loss_kernel(float* __restrict__ out) {
    const int tid  = threadIdx.x;
    const int warp = tid >> 5;
    const int lane = tid & 31;
    const int wm = warp & 1;
    const int wn = warp >> 1;

    const uint32_t sbase = (smem_u32(dyn_smem) + 2047u) & ~2047u;
    const uint32_t sA   = sbase + SMEM_A_OFF;
    const uint32_t sB0  = sbase + SMEM_B0_OFF;
    const uint32_t sB1  = sbase + SMEM_B1_OFF;
    const uint32_t full0  = sbase + SMEM_MBAR_OFF;        // full[0], full[1]
    const uint32_t full1  = full0 + 8;
    const uint32_t empty0 = full0 + 16;                   // empty[0], empty[1]
    const uint32_t empty1 = full0 + 24;

    if (tid == 0) {
        MBARRIER_INIT(full0, 1);
        MBARRIER_INIT(full1, 1);
        MBARRIER_INIT(empty0, 8);
        MBARRIER_INIT(empty1, 8);
    }
    __syncthreads();

    // ldmatrix addressing (swizzled): addr = tile + row*256 + (col ^ (t8<<4))
    const int t8 = lane & 7;
    const uint32_t sxor = (uint32_t)t8 << 4;
    const uint32_t aRow = (uint32_t)(wm * 64 + t8 + ((lane >> 3) & 1) * 8);
    const uint32_t aRB  = aRow * 256;
    const uint32_t aCol = (uint32_t)(lane >> 4) * 16;
    const uint32_t bRow = (uint32_t)(wn * 32 + ((lane >> 4) * 8) + t8);
    const uint32_t bRB  = bRow * 256;
    const uint32_t bCol = (uint32_t)((lane >> 3) & 1) * 16;

    // balanced tile split
    const int per = TOTTILES / GRIDSZ;                 // 13
    const int rem = TOTTILES - per * GRIDSZ;           // 248
    int start, cnt;
    if ((int)blockIdx.x < rem) { cnt = per + 1; start = blockIdx.x * cnt; }
    else                       { cnt = per;     start = rem * (per + 1) + ((int)blockIdx.x - rem) * per; }

    float lsum = 0.0f;
    int cur_bm = -1;

    for (int k = 0; k < cnt; k++) {
        const int t  = start + k;
        const int bm = t >> 6;
        const int bn = t & 63;
        const int buf = t & 1;
        const uint32_t sBcur = buf ? sB1 : sB0;
        const uint32_t fcur  = buf ? full1 : full0;

        if (bm != cur_bm) {
            // rare: everyone must be done with old A before overwrite
            __syncthreads();
            if (tid == 0) {
                const int pf = k >> 1;             // prior fills of this buffer
                if (pf > 0) {
                    const uint32_t ecur = buf ? empty1 : empty0;
                    MBARRIER_WAIT_PARITY_RELAXED(ecur, (pf - 1) & 1);
                }
                MBARRIER_EXPECT_TX(fcur, 2 * TILEB);
                bulk_g2s(sA,    g_xb + (size_t)bm * BM * DDIM, TILEB, fcur);
                bulk_g2s(sBcur, g_yb + (size_t)bn * BN * DDIM, TILEB, fcur);
            }
            cur_bm = bm;
        }

        // producer: fill B(t+1) if next tile shares this A row
        if (tid == 0 && k + 1 < cnt && ((t + 1) >> 6) == bm) {
            const int nbuf = (t + 1) & 1;
            const uint32_t fn = nbuf ? full1 : full0;
            const uint32_t en = nbuf ? empty1 : empty0;
            const int pf = (k + 1) >> 1;           // prior fills of nbuf
            if (pf > 0) MBARRIER_WAIT_PARITY_RELAXED(en, (pf - 1) & 1);
            MBARRIER_EXPECT_TX(fn, TILEB);
            bulk_g2s(nbuf ? sB1 : sB0,
                     g_yb + (size_t)((t + 1) & 63) * BN * DDIM, TILEB, fn);
        }

        // consumer: wait for this tile's data (per-warp, no CTA barrier)
        MBARRIER_WAIT_PARITY(fcur, (k >> 1) & 1);

        // ---- MMA: 8 k-steps of 16 ----
        float acc[4][4][4];
        #pragma unroll
        for (int i = 0; i < 4; i++)
            #pragma unroll
            for (int j = 0; j < 4; j++)
                #pragma unroll
                for (int e = 0; e < 4; e++) acc[i][j][e] = 0.0f;

        #pragma unroll
        for (int ks = 0; ks < 8; ks++) {
            const uint32_t ko = (uint32_t)ks * 32;
            uint32_t a[4][4];
            uint32_t b[2][4];
            #pragma unroll
            for (int mt = 0; mt < 4; mt++)
                ldmatrix_x4(a[mt][0], a[mt][1], a[mt][2], a[mt][3],
                            sA + aRB + (uint32_t)(mt * 4096) + ((aCol + ko) ^ sxor));
            #pragma unroll
            for (int bi = 0; bi < 2; bi++)
                ldmatrix_x4(b[bi][0], b[bi][1], b[bi][2], b[bi][3],
                            sBcur + bRB + (uint32_t)(bi * 4096) + ((bCol + ko) ^ sxor));

            #pragma unroll
            for (int mt = 0; mt < 4; mt++) {
                #pragma unroll
                for (int nt = 0; nt < 4; nt++) {
                    const int bi = nt >> 1;
                    const int po = (nt & 1) * 2;
                    mma16816(acc[mt][nt][0], acc[mt][nt][1], acc[mt][nt][2], acc[mt][nt][3],
                             a[mt][0], a[mt][1], a[mt][2], a[mt][3],
                             b[bi][po], b[bi][po + 1]);
                }
            }
        }

        // this warp is done reading the B buffer (LDSM results all consumed
        // by issued MMAs); release it for the producer
        if (lane == 0) MBARRIER_ARRIVE(buf ? empty1 : empty0);

        // ---- fused loss map (overlaps other warps' MMA) ----
        if (bm != bn) {
            #pragma unroll
            for (int mt = 0; mt < 4; mt++)
                #pragma unroll
                for (int nt = 0; nt < 4; nt++)
                    #pragma unroll
                    for (int e = 0; e < 4; e++)
                        lsum += fmaxf(acc[mt][nt][e], 0.0f);
        } else {
            const int gm0 = wm * 64 + (lane >> 2);
            const int gn0 = wn * 32 + (lane & 3) * 2;
            #pragma unroll
            for (int mt = 0; mt < 4; mt++) {
                const int gmA = gm0 + mt * 16;
                const int gmB = gmA + 8;
                #pragma unroll
                for (int nt = 0; nt < 4; nt++) {
                    const int gn = gn0 + nt * 8;
                    float s0 = acc[mt][nt][0], s1 = acc[mt][nt][1];
                    float s2 = acc[mt][nt][2], s3 = acc[mt][nt][3];
                    lsum += (gmA == gn    ) ? (1.0f - s0) : fmaxf(s0, 0.0f);
                    lsum += (gmA == gn + 1) ? (1.0f - s1) : fmaxf(s1, 0.0f);
                    lsum += (gmB == gn    ) ? (1.0f - s2) : fmaxf(s2, 0.0f);
                    lsum += (gmB == gn + 1) ? (1.0f - s3) : fmaxf(s3, 0.0f);
                }
            }
        }
    }

    // ---- final block reduction + single atomic ----
    #pragma unroll
    for (int o = 16; o > 0; o >>= 1) lsum += __shfl_xor_sync(0xffffffffu, lsum, o);
    float* red = (float*)(uintptr_t)(dyn_smem + (sbase - smem_u32(dyn_smem)) + SMEM_RED_OFF);
    __syncthreads();
    if (lane == 0) red[warp] = lsum;
    __syncthreads();
    if (tid == 0) {
        float tot = 0.0f;
        #pragma unroll
        for (int w = 0; w < 8; w++) tot += red[w];
        atomicAdd(out, tot * INV_N2);
    }
}

// ---------------------------------------------------------------------------
extern "C" void kernel_launch(void* const* d_in, const int* in_sizes, int n_in,
                              void* d_out, int out_size) {
    const float* x = (const float*)d_in[0];
    const float* y = (const float*)d_in[1];
    float* out = (float*)d_out;

    cudaFuncSetAttribute(gemm_loss_kernel,
                         cudaFuncAttributeMaxDynamicSharedMemorySize, SMEM_BYTES);

    cudaMemsetAsync(out, 0, sizeof(float));
    normalize_kernel<<<2 * NROWS / 8, 256>>>(x, y);
    gemm_loss_kernel<<<GRIDSZ, 256, SMEM_BYTES>>>(out);
}

// round 9
// speedup vs baseline: 1.5163x; 1.0078x over previous
#include <cuda_runtime.h>
#include <cuda_bf16.h>
#include <cstdint>

#define NROWS 8192
#define DDIM  128
#define BMT   128                          // macro-tile rows
#define BNT   256                          // macro-tile cols
#define NTM   (NROWS / BMT)                // 64
#define NTN   (NROWS / BNT)                // 32
#define TOTT  (NTM * NTN)                  // 2048
#define GRIDSZ 148                         // 1 CTA per SM
#define INV_N2 1.4901161193847656e-08f     // 2^-26

#define TILEB_A    32768                   // 128 rows x 256B
#define TILEB_B    65536                   // 256 rows x 256B
#define SMEM_A_OFF 0
#define SMEM_B0_OFF TILEB_A                // 32K
#define SMEM_B1_OFF (TILEB_A + TILEB_B)    // 96K
#define SMEM_RED_OFF (TILEB_A + 2 * TILEB_B)   // 160K
#define SMEM_MBAR_OFF (SMEM_RED_OFF + 64)
#define SMEM_BYTES (SMEM_MBAR_OFF + 64 + 2048)

// bf16 normalized copies, PRE-SWIZZLED: 16B chunk v of row r at slot v^(r&7).
__device__ __nv_bfloat16 g_xb[NROWS * DDIM];
__device__ __nv_bfloat16 g_yb[NROWS * DDIM];

__device__ __forceinline__ uint32_t smem_u32(const void* p) {
    uint32_t a;
    asm("{ .reg .u64 t; cvta.to.shared.u64 t, %1; cvt.u32.u64 %0, t; }" : "=r"(a) : "l"(p));
    return a;
}
__device__ __forceinline__ void bulk_g2s(uint32_t dst, const void* src,
                                         uint32_t bytes, uint32_t mbar) {
    asm volatile("cp.async.bulk.shared::cta.global.mbarrier::complete_tx::bytes "
                 "[%0], [%1], %2, [%3];"
                 :: "r"(dst), "l"(src), "r"(bytes), "r"(mbar) : "memory");
}
#define MBARRIER_INIT(mbar, count) \
    asm volatile("mbarrier.init.shared.b64 [%0], %1;" :: "r"((uint32_t)(mbar)), "r"((uint32_t)(count)) : "memory")
#define MBARRIER_EXPECT_TX(mbar, bytes) \
    asm volatile("mbarrier.arrive.expect_tx.shared.b64 _, [%0], %1;" :: "r"((uint32_t)(mbar)), "r"((uint32_t)(bytes)) : "memory")
#define MBARRIER_ARRIVE(mbar) \
    asm volatile("mbarrier.arrive.shared.b64 _, [%0];" :: "r"((uint32_t)(mbar)) : "memory")

#define MBARRIER_WAIT_PARITY(mbar_smem_addr, phase_parity) do { \
    uint32_t _mbar = (uint32_t)(mbar_smem_addr); \
    uint32_t _parity = (uint32_t)(phase_parity); \
    uint32_t _done; \
    asm volatile("{\n\t.reg .pred p;\n\t" \
        "mbarrier.try_wait.parity.acquire.cta.shared::cta.b64 p, [%1], %2;\n\t" \
        "selp.b32 %0, 1, 0, p;\n\t}" : "=r"(_done) : "r"(_mbar), "r"(_parity) : "memory"); \
    if (!_done) { \
        asm volatile("{\n\t.reg .pred P1;\n\t" \
            "WAIT_LOOP_%=:\n\t" \
            "mbarrier.try_wait.parity.acquire.cta.shared::cta.b64 P1, [%0], %1, 0x989680;\n\t" \
            "@P1 bra.uni WAIT_DONE_%=;\n\t" \
            "bra.uni WAIT_LOOP_%=;\n\t" \
            "WAIT_DONE_%=:\n\t}" :: "r"(_mbar), "r"(_parity) : "memory"); \
    } \
} while(0)

// Relaxed: producer-only; post-wait smem access is async-proxy (bulk copy).
#define MBARRIER_WAIT_PARITY_RELAXED(mbar_smem_addr, phase_parity) do { \
    uint32_t _mbar = (uint32_t)(mbar_smem_addr); \
    uint32_t _parity = (uint32_t)(phase_parity); \
    uint32_t _done; \
    asm volatile("{\n\t.reg .pred p;\n\t" \
        "mbarrier.try_wait.parity.relaxed.cta.shared::cta.b64 p, [%1], %2, 0x989680;\n\t" \
        "selp.b32 %0, 1, 0, p;\n\t}" : "=r"(_done) : "r"(_mbar), "r"(_parity) : "memory"); \
    if (!_done) { \
        asm volatile("{\n\t.reg .pred P1;\n\t" \
            "WAIT_LOOP_%=:\n\t" \
            "mbarrier.try_wait.parity.relaxed.cta.shared::cta.b64 P1, [%0], %1, 0x989680;\n\t" \
            "@P1 bra.uni WAIT_DONE_%=;\n\t" \
            "bra.uni WAIT_LOOP_%=;\n\t" \
            "WAIT_DONE_%=:\n\t}" :: "r"(_mbar), "r"(_parity) : "memory"); \
    } \
} while(0)

__device__ __forceinline__ void ldmatrix_x4(uint32_t& r0, uint32_t& r1,
                                            uint32_t& r2, uint32_t& r3, uint32_t addr) {
    asm volatile("ldmatrix.sync.aligned.m8n8.x4.shared.b16 {%0,%1,%2,%3}, [%4];"
                 : "=r"(r0), "=r"(r1), "=r"(r2), "=r"(r3) : "r"(addr));
}
__device__ __forceinline__ void mma16816(float& d0, float& d1, float& d2, float& d3,
                                         uint32_t a0, uint32_t a1, uint32_t a2, uint32_t a3,
                                         uint32_t b0, uint32_t b1) {
    asm volatile("mma.sync.aligned.m16n8k16.row.col.f32.bf16.bf16.f32 "
                 "{%0,%1,%2,%3}, {%4,%5,%6,%7}, {%8,%9}, {%0,%1,%2,%3};"
                 : "+f"(d0), "+f"(d1), "+f"(d2), "+f"(d3)
                 : "r"(a0), "r"(a1), "r"(a2), "r"(a3), "r"(b0), "r"(b1));
}

// ---------------------------------------------------------------------------
// Kernel A: warp-per-row normalize; writes swizzled gmem layout.
// ---------------------------------------------------------------------------
__global__ void __launch_bounds__(256)
normalize_kernel(const float* __restrict__ x, const float* __restrict__ y) {
    const int row  = blockIdx.x * 8 + (threadIdx.x >> 5);
    const int lane = threadIdx.x & 31;
    const float* src;
    __nv_bfloat16* dst;
    if (row < NROWS) { src = x + (size_t)row * DDIM;           dst = g_xb + (size_t)row * DDIM; }
    else             { src = y + (size_t)(row - NROWS) * DDIM; dst = g_yb + (size_t)(row - NROWS) * DDIM; }

    float4 v = ((const float4*)src)[lane];
    float ss = v.x * v.x + v.y * v.y + v.z * v.z + v.w * v.w;
    #pragma unroll
    for (int o = 16; o > 0; o >>= 1) ss += __shfl_xor_sync(0xffffffffu, ss, o);
    float r = rsqrtf(fmaxf(ss, 1e-24f));

    __nv_bfloat162 p0 = __floats2bfloat162_rn(v.x * r, v.y * r);
    __nv_bfloat162 p1 = __floats2bfloat162_rn(v.z * r, v.w * r);
    uint2 pk;
    pk.x = *(uint32_t*)&p0;
    pk.y = *(uint32_t*)&p1;

    const int vchunk = lane >> 1;
    const int half   = lane & 1;
    const int schunk = vchunk ^ (row & 7);
    ((uint2*)dst)[schunk * 2 + half] = pk;
}

// ---------------------------------------------------------------------------
// Kernel B: persistent bf16 mma.sync GEMM + fused loss.
// CTA macro-tile 128x256; 8 warps 2(m) x 4(n), warp tile 64x64.
// Per-warp producer/consumer mbarrier pipeline (full count 1 + expect_tx,
// empty count 8); B double-buffered (64KB each), one bulk copy per tile.
// ---------------------------------------------------------------------------
extern __shared__ char dyn_smem[];

__global__ void __launch_bounds__(256, 1)
gemm_loss_kernel(float* __restrict__ out) {
    const int tid  = threadIdx.x;
    const int warp = tid >> 5;
    const int lane = tid & 31;
    const int wm = warp >> 2;          // 0..1  (64-row half)
    const int wn = warp & 3;           // 0..3  (64-col quarter)

    const uint32_t sbase = (smem_u32(dyn_smem) + 2047u) & ~2047u;
    const uint32_t sA   = sbase + SMEM_A_OFF;
    const uint32_t sB0  = sbase + SMEM_B0_OFF;
    const uint32_t sB1  = sbase + SMEM_B1_OFF;
    const uint32_t full0  = sbase + SMEM_MBAR_OFF;
    const uint32_t full1  = full0 + 8;
    const uint32_t empty0 = full0 + 16;
    const uint32_t empty1 = full0 + 24;

    if (tid == 0) {
        MBARRIER_INIT(full0, 1);
        MBARRIER_INIT(full1, 1);
        MBARRIER_INIT(empty0, 8);
        MBARRIER_INIT(empty1, 8);
    }
    __syncthreads();

    // ldmatrix addressing (swizzled): addr = tile + row*256 + (col ^ (t8<<4))
    const int t8 = lane & 7;
    const uint32_t sxor = (uint32_t)t8 << 4;
    const uint32_t aRow = (uint32_t)(wm * 64 + t8 + ((lane >> 3) & 1) * 8);
    const uint32_t aRB  = aRow * 256;
    const uint32_t aCol = (uint32_t)(lane >> 4) * 16;
    const uint32_t bRow = (uint32_t)(wn * 64 + ((lane >> 4) * 8) + t8);
    const uint32_t bRB  = bRow * 256;
    const uint32_t bCol = (uint32_t)((lane >> 3) & 1) * 16;

    // balanced tile split: 2048 tiles over 148 CTAs
    const int per = TOTT / GRIDSZ;                 // 13
    const int rem = TOTT - per * GRIDSZ;           // 124
    int start, cnt;
    if ((int)blockIdx.x < rem) { cnt = per + 1; start = blockIdx.x * cnt; }
    else                       { cnt = per;     start = rem * (per + 1) + ((int)blockIdx.x - rem) * per; }

    float lsum = 0.0f;
    int cur_bm = -1;

    for (int k = 0; k < cnt; k++) {
        const int t  = start + k;
        const int bm = t >> 5;                     // 32 n-tiles per bm row
        const int bn = t & 31;
        const int buf = t & 1;
        const uint32_t sBcur = buf ? sB1 : sB0;
        const uint32_t fcur  = buf ? full1 : full0;

        if (bm != cur_bm) {
            __syncthreads();                       // rare: old A must be dead
            if (tid == 0) {
                const int pf = k >> 1;
                if (pf > 0) {
                    const uint32_t ecur = buf ? empty1 : empty0;
                    MBARRIER_WAIT_PARITY_RELAXED(ecur, (pf - 1) & 1);
                }
                MBARRIER_EXPECT_TX(fcur, TILEB_A + TILEB_B);
                bulk_g2s(sA,    g_xb + (size_t)bm * BMT * DDIM, TILEB_A, fcur);
                bulk_g2s(sBcur, g_yb + (size_t)bn * BNT * DDIM, TILEB_B, fcur);
            }
            cur_bm = bm;
        }

        // producer: fill B(t+1) if next tile shares this A row
        if (tid == 0 && k + 1 < cnt && ((t + 1) >> 5) == bm) {
            const int nbuf = (t + 1) & 1;
            const uint32_t fn = nbuf ? full1 : full0;
            const uint32_t en = nbuf ? empty1 : empty0;
            const int pf = (k + 1) >> 1;
            if (pf > 0) MBARRIER_WAIT_PARITY_RELAXED(en, (pf - 1) & 1);
            MBARRIER_EXPECT_TX(fn, TILEB_B);
            bulk_g2s(nbuf ? sB1 : sB0,
                     g_yb + (size_t)((t + 1) & 31) * BNT * DDIM, TILEB_B, fn);
        }

        // consumer: per-warp wait for this tile's data
        MBARRIER_WAIT_PARITY(fcur, (k >> 1) & 1);

        // ---- MMA: 8 k-steps of 16; per step 8 LDSM feed 32 MMAs ----
        float acc[4][8][4];
        #pragma unroll
        for (int i = 0; i < 4; i++)
            #pragma unroll
            for (int j = 0; j < 8; j++)
                #pragma unroll
                for (int e = 0; e < 4; e++) acc[i][j][e] = 0.0f;

        #pragma unroll
        for (int ks = 0; ks < 8; ks++) {
            const uint32_t ko = (uint32_t)ks * 32;
            uint32_t a[4][4];
            uint32_t b[4][4];
            #pragma unroll
            for (int mt = 0; mt < 4; mt++)
                ldmatrix_x4(a[mt][0], a[mt][1], a[mt][2], a[mt][3],
                            sA + aRB + (uint32_t)(mt * 4096) + ((aCol + ko) ^ sxor));
            #pragma unroll
            for (int bi = 0; bi < 4; bi++)
                ldmatrix_x4(b[bi][0], b[bi][1], b[bi][2], b[bi][3],
                            sBcur + bRB + (uint32_t)(bi * 4096) + ((bCol + ko) ^ sxor));

            #pragma unroll
            for (int mt = 0; mt < 4; mt++) {
                #pragma unroll
                for (int nt = 0; nt < 8; nt++) {
                    const int bi = nt >> 1;
                    const int po = (nt & 1) * 2;
                    mma16816(acc[mt][nt][0], acc[mt][nt][1], acc[mt][nt][2], acc[mt][nt][3],
                             a[mt][0], a[mt][1], a[mt][2], a[mt][3],
                             b[bi][po], b[bi][po + 1]);
                }
            }
        }

        // release B buffer for the producer
        if (lane == 0) MBARRIER_ARRIVE(buf ? empty1 : empty0);

        // ---- fused loss map ----
        if ((bm >> 1) != bn) {
            #pragma unroll
            for (int mt = 0; mt < 4; mt++)
                #pragma unroll
                for (int nt = 0; nt < 8; nt++)
                    #pragma unroll
                    for (int e = 0; e < 4; e++)
                        lsum += fmaxf(acc[mt][nt][e], 0.0f);
        } else {
            const int gm0 = bm * BMT + wm * 64 + (lane >> 2);
            const int gn0 = bn * BNT + wn * 64 + (lane & 3) * 2;
            #pragma unroll
            for (int mt = 0; mt < 4; mt++) {
                const int gmA = gm0 + mt * 16;
                const int gmB = gmA + 8;
                #pragma unroll
                for (int nt = 0; nt < 8; nt++) {
                    const int gn = gn0 + nt * 8;
                    float s0 = acc[mt][nt][0], s1 = acc[mt][nt][1];
                    float s2 = acc[mt][nt][2], s3 = acc[mt][nt][3];
                    lsum += (gmA == gn    ) ? (1.0f - s0) : fmaxf(s0, 0.0f);
                    lsum += (gmA == gn + 1) ? (1.0f - s1) : fmaxf(s1, 0.0f);
                    lsum += (gmB == gn    ) ? (1.0f - s2) : fmaxf(s2, 0.0f);
                    lsum += (gmB == gn + 1) ? (1.0f - s3) : fmaxf(s3, 0.0f);
                }
            }
        }
    }

    // ---- final block reduction + single atomic ----
    #pragma unroll
    for (int o = 16; o > 0; o >>= 1) lsum += __shfl_xor_sync(0xffffffffu, lsum, o);
    float* red = (float*)(uintptr_t)(dyn_smem + (sbase - smem_u32(dyn_smem)) + SMEM_RED_OFF);
    __syncthreads();
    if (lane == 0) red[warp] = lsum;
    __syncthreads();
    if (tid == 0) {
        float tot = 0.0f;
        #pragma unroll
        for (int w = 0; w < 8; w++) tot += red[w];
        atomicAdd(out, tot * INV_N2);
    }
}

// ---------------------------------------------------------------------------
extern "C" void kernel_launch(void* const* d_in, const int* in_sizes, int n_in,
                              void* d_out, int out_size) {
    const float* x = (const float*)d_in[0];
    const float* y = (const float*)d_in[1];
    float* out = (float*)d_out;

    cudaFuncSetAttribute(gemm_loss_kernel,
                         cudaFuncAttributeMaxDynamicSharedMemorySize, SMEM_BYTES);

    cudaMemsetAsync(out, 0, sizeof(float));
    normalize_kernel<<<2 * NROWS / 8, 256>>>(x, y);
    gemm_loss_kernel<<<GRIDSZ, 256, SMEM_BYTES>>>(out);
}

// round 10
// speedup vs baseline: 1.5173x; 1.0007x over previous
#include <cuda_runtime.h>
#include <cuda_bf16.h>
#include <cstdint>

#define NROWS 8192
#define DDIM  128
#define BMT   128                          // macro-tile rows
#define BNT   256                          // macro-tile cols
#define NTM   (NROWS / BMT)                // 64
#define NTN   (NROWS / BNT)                // 32
#define TOTT  (NTM * NTN)                  // 2048
#define GRIDSZ 148                         // 1 CTA per SM
#define INV_N2 1.4901161193847656e-08f     // 2^-26

#define TILEB_A    32768                   // 128 rows x 256B
#define TILEB_B    65536                   // 256 rows x 256B
#define SMEM_A_OFF 0
#define SMEM_B0_OFF TILEB_A                // 32K
#define SMEM_B1_OFF (TILEB_A + TILEB_B)    // 96K
#define SMEM_RED_OFF (TILEB_A + 2 * TILEB_B)   // 160K
#define SMEM_MBAR_OFF (SMEM_RED_OFF + 64)
#define SMEM_BYTES (SMEM_MBAR_OFF + 64 + 2048)

// bf16 normalized copies, PRE-SWIZZLED: 16B chunk v of row r at slot v^(r&7).
__device__ __nv_bfloat16 g_xb[NROWS * DDIM];
__device__ __nv_bfloat16 g_yb[NROWS * DDIM];

__device__ __forceinline__ uint32_t smem_u32(const void* p) {
    uint32_t a;
    asm("{ .reg .u64 t; cvta.to.shared.u64 t, %1; cvt.u32.u64 %0, t; }" : "=r"(a) : "l"(p));
    return a;
}
__device__ __forceinline__ void bulk_g2s(uint32_t dst, const void* src,
                                         uint32_t bytes, uint32_t mbar) {
    asm volatile("cp.async.bulk.shared::cta.global.mbarrier::complete_tx::bytes "
                 "[%0], [%1], %2, [%3];"
                 :: "r"(dst), "l"(src), "r"(bytes), "r"(mbar) : "memory");
}
#define MBARRIER_INIT(mbar, count) \
    asm volatile("mbarrier.init.shared.b64 [%0], %1;" :: "r"((uint32_t)(mbar)), "r"((uint32_t)(count)) : "memory")
#define MBARRIER_EXPECT_TX(mbar, bytes) \
    asm volatile("mbarrier.arrive.expect_tx.shared.b64 _, [%0], %1;" :: "r"((uint32_t)(mbar)), "r"((uint32_t)(bytes)) : "memory")
#define MBARRIER_ARRIVE(mbar) \
    asm volatile("mbarrier.arrive.shared.b64 _, [%0];" :: "r"((uint32_t)(mbar)) : "memory")

#define MBARRIER_WAIT_PARITY(mbar_smem_addr, phase_parity) do { \
    uint32_t _mbar = (uint32_t)(mbar_smem_addr); \
    uint32_t _parity = (uint32_t)(phase_parity); \
    uint32_t _done; \
    asm volatile("{\n\t.reg .pred p;\n\t" \
        "mbarrier.try_wait.parity.acquire.cta.shared::cta.b64 p, [%1], %2;\n\t" \
        "selp.b32 %0, 1, 0, p;\n\t}" : "=r"(_done) : "r"(_mbar), "r"(_parity) : "memory"); \
    if (!_done) { \
        asm volatile("{\n\t.reg .pred P1;\n\t" \
            "WAIT_LOOP_%=:\n\t" \
            "mbarrier.try_wait.parity.acquire.cta.shared::cta.b64 P1, [%0], %1, 0x989680;\n\t" \
            "@P1 bra.uni WAIT_DONE_%=;\n\t" \
            "bra.uni WAIT_LOOP_%=;\n\t" \
            "WAIT_DONE_%=:\n\t}" :: "r"(_mbar), "r"(_parity) : "memory"); \
    } \
} while(0)

// Relaxed: producer-only; post-wait smem access is async-proxy (bulk copy).
#define MBARRIER_WAIT_PARITY_RELAXED(mbar_smem_addr, phase_parity) do { \
    uint32_t _mbar = (uint32_t)(mbar_smem_addr); \
    uint32_t _parity = (uint32_t)(phase_parity); \
    uint32_t _done; \
    asm volatile("{\n\t.reg .pred p;\n\t" \
        "mbarrier.try_wait.parity.relaxed.cta.shared::cta.b64 p, [%1], %2, 0x989680;\n\t" \
        "selp.b32 %0, 1, 0, p;\n\t}" : "=r"(_done) : "r"(_mbar), "r"(_parity) : "memory"); \
    if (!_done) { \
        asm volatile("{\n\t.reg .pred P1;\n\t" \
            "WAIT_LOOP_%=:\n\t" \
            "mbarrier.try_wait.parity.relaxed.cta.shared::cta.b64 P1, [%0], %1, 0x989680;\n\t" \
            "@P1 bra.uni WAIT_DONE_%=;\n\t" \
            "bra.uni WAIT_LOOP_%=;\n\t" \
            "WAIT_DONE_%=:\n\t}" :: "r"(_mbar), "r"(_parity) : "memory"); \
    } \
} while(0)

__device__ __forceinline__ void ldmatrix_x4(uint32_t& r0, uint32_t& r1,
                                            uint32_t& r2, uint32_t& r3, uint32_t addr) {
    asm volatile("ldmatrix.sync.aligned.m8n8.x4.shared.b16 {%0,%1,%2,%3}, [%4];"
                 : "=r"(r0), "=r"(r1), "=r"(r2), "=r"(r3) : "r"(addr));
}
__device__ __forceinline__ void mma16816(float& d0, float& d1, float& d2, float& d3,
                                         uint32_t a0, uint32_t a1, uint32_t a2, uint32_t a3,
                                         uint32_t b0, uint32_t b1) {
    asm volatile("mma.sync.aligned.m16n8k16.row.col.f32.bf16.bf16.f32 "
                 "{%0,%1,%2,%3}, {%4,%5,%6,%7}, {%8,%9}, {%0,%1,%2,%3};"
                 : "+f"(d0), "+f"(d1), "+f"(d2), "+f"(d3)
                 : "r"(a0), "r"(a1), "r"(a2), "r"(a3), "r"(b0), "r"(b1));
}

// ---------------------------------------------------------------------------
// Kernel A: warp-per-row normalize; writes swizzled gmem layout.
// ---------------------------------------------------------------------------
__global__ void __launch_bounds__(256)
normalize_kernel(const float* __restrict__ x, const float* __restrict__ y) {
    const int row  = blockIdx.x * 8 + (threadIdx.x >> 5);
    const int lane = threadIdx.x & 31;
    const float* src;
    __nv_bfloat16* dst;
    if (row < NROWS) { src = x + (size_t)row * DDIM;           dst = g_xb + (size_t)row * DDIM; }
    else             { src = y + (size_t)(row - NROWS) * DDIM; dst = g_yb + (size_t)(row - NROWS) * DDIM; }

    float4 v = ((const float4*)src)[lane];
    float ss = v.x * v.x + v.y * v.y + v.z * v.z + v.w * v.w;
    #pragma unroll
    for (int o = 16; o > 0; o >>= 1) ss += __shfl_xor_sync(0xffffffffu, ss, o);
    float r = rsqrtf(fmaxf(ss, 1e-24f));

    __nv_bfloat162 p0 = __floats2bfloat162_rn(v.x * r, v.y * r);
    __nv_bfloat162 p1 = __floats2bfloat162_rn(v.z * r, v.w * r);
    uint2 pk;
    pk.x = *(uint32_t*)&p0;
    pk.y = *(uint32_t*)&p1;

    const int vchunk = lane >> 1;
    const int half   = lane & 1;
    const int schunk = vchunk ^ (row & 7);
    ((uint2*)dst)[schunk * 2 + half] = pk;
}

// ---------------------------------------------------------------------------
// Kernel B: persistent bf16 mma.sync GEMM + fused loss.
// CTA macro-tile 128x256; 8 warps 2(m) x 4(n), warp tile 64x64.
// Per-warp producer/consumer mbarrier pipeline; B double-buffered.
// Epilogue uses 8 persistent partial sums (no serial FADD chain); the
// B-buffer empty-arrive fires right after the final k-step's LDSMs.
// ---------------------------------------------------------------------------
extern __shared__ char dyn_smem[];

__global__ void __launch_bounds__(256, 1)
gemm_loss_kernel(float* __restrict__ out) {
    const int tid  = threadIdx.x;
    const int warp = tid >> 5;
    const int lane = tid & 31;
    const int wm = warp >> 2;          // 0..1  (64-row half)
    const int wn = warp & 3;           // 0..3  (64-col quarter)

    const uint32_t sbase = (smem_u32(dyn_smem) + 2047u) & ~2047u;
    const uint32_t sA   = sbase + SMEM_A_OFF;
    const uint32_t sB0  = sbase + SMEM_B0_OFF;
    const uint32_t sB1  = sbase + SMEM_B1_OFF;
    const uint32_t full0  = sbase + SMEM_MBAR_OFF;
    const uint32_t full1  = full0 + 8;
    const uint32_t empty0 = full0 + 16;
    const uint32_t empty1 = full0 + 24;

    if (tid == 0) {
        MBARRIER_INIT(full0, 1);
        MBARRIER_INIT(full1, 1);
        MBARRIER_INIT(empty0, 8);
        MBARRIER_INIT(empty1, 8);
    }
    __syncthreads();

    // ldmatrix addressing (swizzled): addr = tile + row*256 + (col ^ (t8<<4))
    const int t8 = lane & 7;
    const uint32_t sxor = (uint32_t)t8 << 4;
    const uint32_t aRow = (uint32_t)(wm * 64 + t8 + ((lane >> 3) & 1) * 8);
    const uint32_t aRB  = aRow * 256;
    const uint32_t aCol = (uint32_t)(lane >> 4) * 16;
    const uint32_t bRow = (uint32_t)(wn * 64 + ((lane >> 4) * 8) + t8);
    const uint32_t bRB  = bRow * 256;
    const uint32_t bCol = (uint32_t)((lane >> 3) & 1) * 16;

    // balanced tile split: 2048 tiles over 148 CTAs
    const int per = TOTT / GRIDSZ;                 // 13
    const int rem = TOTT - per * GRIDSZ;           // 124
    int start, cnt;
    if ((int)blockIdx.x < rem) { cnt = per + 1; start = blockIdx.x * cnt; }
    else                       { cnt = per;     start = rem * (per + 1) + ((int)blockIdx.x - rem) * per; }

    // 8 persistent partial sums: breaks the serial FADD dependency chain.
    float ps[8];
    #pragma unroll
    for (int i = 0; i < 8; i++) ps[i] = 0.0f;

    int cur_bm = -1;

    for (int k = 0; k < cnt; k++) {
        const int t  = start + k;
        const int bm = t >> 5;                     // 32 n-tiles per bm row
        const int bn = t & 31;
        const int buf = t & 1;
        const uint32_t sBcur = buf ? sB1 : sB0;
        const uint32_t fcur  = buf ? full1 : full0;

        if (bm != cur_bm) {
            __syncthreads();                       // rare: old A must be dead
            if (tid == 0) {
                const int pf = k >> 1;
                if (pf > 0) {
                    const uint32_t ecur = buf ? empty1 : empty0;
                    MBARRIER_WAIT_PARITY_RELAXED(ecur, (pf - 1) & 1);
                }
                MBARRIER_EXPECT_TX(fcur, TILEB_A + TILEB_B);
                bulk_g2s(sA,    g_xb + (size_t)bm * BMT * DDIM, TILEB_A, fcur);
                bulk_g2s(sBcur, g_yb + (size_t)bn * BNT * DDIM, TILEB_B, fcur);
            }
            cur_bm = bm;
        }

        // producer: fill B(t+1) if next tile shares this A row
        if (tid == 0 && k + 1 < cnt && ((t + 1) >> 5) == bm) {
            const int nbuf = (t + 1) & 1;
            const uint32_t fn = nbuf ? full1 : full0;
            const uint32_t en = nbuf ? empty1 : empty0;
            const int pf = (k + 1) >> 1;
            if (pf > 0) MBARRIER_WAIT_PARITY_RELAXED(en, (pf - 1) & 1);
            MBARRIER_EXPECT_TX(fn, TILEB_B);
            bulk_g2s(nbuf ? sB1 : sB0,
                     g_yb + (size_t)((t + 1) & 31) * BNT * DDIM, TILEB_B, fn);
        }

        // consumer: per-warp wait for this tile's data
        MBARRIER_WAIT_PARITY(fcur, (k >> 1) & 1);

        // ---- MMA: 8 k-steps of 16; per step 8 LDSM feed 32 MMAs ----
        float acc[4][8][4];
        #pragma unroll
        for (int i = 0; i < 4; i++)
            #pragma unroll
            for (int j = 0; j < 8; j++)
                #pragma unroll
                for (int e = 0; e < 4; e++) acc[i][j][e] = 0.0f;

        #pragma unroll
        for (int ks = 0; ks < 8; ks++) {
            const uint32_t ko = (uint32_t)ks * 32;
            uint32_t a[4][4];
            uint32_t b[4][4];
            #pragma unroll
            for (int mt = 0; mt < 4; mt++)
                ldmatrix_x4(a[mt][0], a[mt][1], a[mt][2], a[mt][3],
                            sA + aRB + (uint32_t)(mt * 4096) + ((aCol + ko) ^ sxor));
            #pragma unroll
            for (int bi = 0; bi < 4; bi++)
                ldmatrix_x4(b[bi][0], b[bi][1], b[bi][2], b[bi][3],
                            sBcur + bRB + (uint32_t)(bi * 4096) + ((bCol + ko) ^ sxor));

            // after the last k-step's LDSMs the B buffer contents are fully
            // captured in registers: release it early for the producer.
            if (ks == 7 && lane == 0) MBARRIER_ARRIVE(buf ? empty1 : empty0);

            #pragma unroll
            for (int mt = 0; mt < 4; mt++) {
                #pragma unroll
                for (int nt = 0; nt < 8; nt++) {
                    const int bi = nt >> 1;
                    const int po = (nt & 1) * 2;
                    mma16816(acc[mt][nt][0], acc[mt][nt][1], acc[mt][nt][2], acc[mt][nt][3],
                             a[mt][0], a[mt][1], a[mt][2], a[mt][3],
                             b[bi][po], b[bi][po + 1]);
                }
            }
        }

        // ---- fused loss map into rotating partials ----
        if ((bm >> 1) != bn) {
            #pragma unroll
            for (int mt = 0; mt < 4; mt++)
                #pragma unroll
                for (int nt = 0; nt < 8; nt++)
                    #pragma unroll
                    for (int e = 0; e < 4; e++)
                        ps[((nt & 1) << 2) | e] += fmaxf(acc[mt][nt][e], 0.0f);
        } else {
            const int gm0 = bm * BMT + wm * 64 + (lane >> 2);
            const int gn0 = bn * BNT + wn * 64 + (lane & 3) * 2;
            #pragma unroll
            for (int mt = 0; mt < 4; mt++) {
                const int gmA = gm0 + mt * 16;
                const int gmB = gmA + 8;
                #pragma unroll
                for (int nt = 0; nt < 8; nt++) {
                    const int gn = gn0 + nt * 8;
                    float s0 = acc[mt][nt][0], s1 = acc[mt][nt][1];
                    float s2 = acc[mt][nt][2], s3 = acc[mt][nt][3];
                    const int pb = (nt & 1) << 2;
                    ps[pb | 0] += (gmA == gn    ) ? (1.0f - s0) : fmaxf(s0, 0.0f);
                    ps[pb | 1] += (gmA == gn + 1) ? (1.0f - s1) : fmaxf(s1, 0.0f);
                    ps[pb | 2] += (gmB == gn    ) ? (1.0f - s2) : fmaxf(s2, 0.0f);
                    ps[pb | 3] += (gmB == gn + 1) ? (1.0f - s3) : fmaxf(s3, 0.0f);
                }
            }
        }
    }

    // ---- combine partials, block reduction + single atomic ----
    float lsum = ((ps[0] + ps[1]) + (ps[2] + ps[3]))
               + ((ps[4] + ps[5]) + (ps[6] + ps[7]));
    #pragma unroll
    for (int o = 16; o > 0; o >>= 1) lsum += __shfl_xor_sync(0xffffffffu, lsum, o);
    float* red = (float*)(uintptr_t)(dyn_smem + (sbase - smem_u32(dyn_smem)) + SMEM_RED_OFF);
    __syncthreads();
    if (lane == 0) red[warp] = lsum;
    __syncthreads();
    if (tid == 0) {
        float tot = 0.0f;
        #pragma unroll
        for (int w = 0; w < 8; w++) tot += red[w];
        atomicAdd(out, tot * INV_N2);
    }
}

// ---------------------------------------------------------------------------
extern "C" void kernel_launch(void* const* d_in, const int* in_sizes, int n_in,
                              void* d_out, int out_size) {
    const float* x = (const float*)d_in[0];
    const float* y = (const float*)d_in[1];
    float* out = (float*)d_out;

    cudaFuncSetAttribute(gemm_loss_kernel,
                         cudaFuncAttributeMaxDynamicSharedMemorySize, SMEM_BYTES);

    cudaMemsetAsync(out, 0, sizeof(float));
    normalize_kernel<<<2 * NROWS / 8, 256>>>(x, y);
    gemm_loss_kernel<<<GRIDSZ, 256, SMEM_BYTES>>>(out);
}